// round 2
// baseline (speedup 1.0000x reference)
#include <cuda_runtime.h>

// LSTM: B=512, T=512, D=32, H=64.  One CTA (256 threads) per batch element.
// Thread g owns gate row g (i:0-63, f:64-127, g:128-191, o:192-255) with
// W_ih[g,:] (32 fp32) and W_hh[g,:] (64 fp32) register-resident as f32x2 pairs.
// Per step: every thread does a fused 96-MAC dot (48 fma.rn.f32x2) reading
// x_t and h_{t-1} from SMEM broadcasts, applies its gate activation, STS;
// threads 0..63 then update c,h, write hs, and reduce the sigmoid head.

#define B_ 512
#define T_ 512
#define D_ 32
#define H_ 64

typedef unsigned long long u64;

__device__ __forceinline__ u64 fma2(u64 a, u64 b, u64 c) {
    u64 d;
    asm("fma.rn.f32x2 %0, %1, %2, %3;" : "=l"(d) : "l"(a), "l"(b), "l"(c));
    return d;
}
__device__ __forceinline__ u64 add2(u64 a, u64 b) {
    u64 d;
    asm("add.rn.f32x2 %0, %1, %2;" : "=l"(d) : "l"(a), "l"(b));
    return d;
}
__device__ __forceinline__ float lo32(u64 a) { return __uint_as_float((unsigned)a); }
__device__ __forceinline__ float hi32(u64 a) { return __uint_as_float((unsigned)(a >> 32)); }

__device__ __forceinline__ float sigmoid_(float x) {
    // 1/(1+e^-x); __expf -> MUFU.EX2, __fdividef -> MUFU.RCP.
    // x << 0: e^-x -> inf, __fdividef(1,inf)=0  (correct limit)
    return __fdividef(1.f, 1.f + __expf(-x));
}
__device__ __forceinline__ float tanh_(float x) {
    // sign-safe: tanh(|x|) = 1 - 2/(e^{2|x|}+1); e -> inf gives exactly 1.
    float ax = fabsf(x);
    float t = 1.f - __fdividef(2.f, __expf(2.f * ax) + 1.f);
    return copysignf(t, x);
}

__global__ __launch_bounds__(256, 2) void lstm_fused_kernel(
    const float* __restrict__ x,     // [B,T,D]
    const float* __restrict__ h0,    // [1,B,H]
    const float* __restrict__ c0,    // [1,B,H]
    const float* __restrict__ Wih,   // [4H,D]
    const float* __restrict__ Whh,   // [4H,H]
    const float* __restrict__ bih,   // [4H]
    const float* __restrict__ bhh,   // [4H]
    const float* __restrict__ Wout,  // [1,H]
    const float* __restrict__ bout,  // [1]
    float* __restrict__ out0,        // [B,T]   (sigmoid head)
    float* __restrict__ hs,          // [B,T,H] (hidden states)
    int write_out0, int write_hs)
{
    __shared__ __align__(16) float h_sm[H_];
    __shared__ __align__(16) float x_sm[2][D_];
    __shared__ __align__(16) float act_sm[256];
    __shared__ float red_sm[2];

    const int b = blockIdx.x;
    const int tid = threadIdx.x;
    const int g = tid;  // gate row index 0..255

    // ---- load weights into registers as packed f32x2 pairs ----
    u64 wih[16], whh[32];
    {
        const ulonglong2* p = reinterpret_cast<const ulonglong2*>(Wih + g * D_);
#pragma unroll
        for (int q = 0; q < 8; q++) {
            ulonglong2 v = p[q];
            wih[2 * q] = v.x;
            wih[2 * q + 1] = v.y;
        }
        const ulonglong2* p2 = reinterpret_cast<const ulonglong2*>(Whh + g * H_);
#pragma unroll
        for (int q = 0; q < 16; q++) {
            ulonglong2 v = p2[q];
            whh[2 * q] = v.x;
            whh[2 * q + 1] = v.y;
        }
    }
    const float bias = bih[g] + bhh[g];
    const bool is_tanh_gate = ((g >> 6) == 2);  // gate block 2 = candidate 'g'

    float c = 0.f, wout = 0.f;
    if (tid < H_) {
        c = c0[b * H_ + tid];
        h_sm[tid] = h0[b * H_ + tid];
        wout = Wout[tid];
    }
    if (tid >= 224) {  // warp 7 owns x staging
        x_sm[0][tid - 224] = x[(b * T_ + 0) * D_ + (tid - 224)];
    }
    const float bo = bout[0];
    __syncthreads();

    for (int t = 0; t < T_; t++) {
        // ---- prefetch x for step t+1 (issued early to overlap the dot) ----
        float xn = 0.f;
        if (tid >= 224) {
            int tt = (t + 1 < T_) ? (t + 1) : t;
            xn = x[(b * T_ + tt) * D_ + (tid - 224)];
        }

        // ---- fused gate pre-activation: W_ih[g,:]@x_t + W_hh[g,:]@h + bias ----
        u64 a0 = 0, a1 = 0, a2 = 0, a3 = 0;
        const ulonglong2* xv = reinterpret_cast<const ulonglong2*>(x_sm[t & 1]);
#pragma unroll
        for (int q = 0; q < 8; q++) {
            ulonglong2 v = xv[q];  // LDS.128 broadcast
            a0 = fma2(wih[2 * q], v.x, a0);
            a1 = fma2(wih[2 * q + 1], v.y, a1);
        }
        const ulonglong2* hv = reinterpret_cast<const ulonglong2*>(h_sm);
#pragma unroll
        for (int q = 0; q < 16; q++) {
            ulonglong2 v = hv[q];  // LDS.128 broadcast
            a2 = fma2(whh[2 * q], v.x, a2);
            a3 = fma2(whh[2 * q + 1], v.y, a3);
        }
        u64 s = add2(add2(a0, a1), add2(a2, a3));
        float pre = lo32(s) + hi32(s) + bias;

        float act = is_tanh_gate ? tanh_(pre) : sigmoid_(pre);
        act_sm[g] = act;
        if (tid >= 224) x_sm[(t + 1) & 1][tid - 224] = xn;
        __syncthreads();  // bar1: gates + next-x visible

        // ---- state update + outputs (threads 0..63, i.e. warps 0-1) ----
        if (tid < H_) {
            float iv = act_sm[tid];
            float fv = act_sm[H_ + tid];
            float gv = act_sm[2 * H_ + tid];
            float ov = act_sm[3 * H_ + tid];
            c = fv * c + iv * gv;
            float h = ov * tanh_(c);
            h_sm[tid] = h;
            if (write_hs) hs[(b * T_ + t) * H_ + tid] = h;
            // sigmoid head: dot(h, W_out) across 64 lanes (2 full warps)
            float p = h * wout;
#pragma unroll
            for (int off = 16; off; off >>= 1)
                p += __shfl_down_sync(0xffffffffu, p, off);
            if ((tid & 31) == 0) red_sm[tid >> 5] = p;
        }
        __syncthreads();  // bar2: h_sm + head partials visible

        if (tid == 0 && write_out0) {
            out0[b * T_ + t] = sigmoid_(red_sm[0] + red_sm[1] + bo);
        }
    }
}

extern "C" void kernel_launch(void* const* d_in, const int* in_sizes, int n_in,
                              void* d_out, int out_size) {
    const float* x    = (const float*)d_in[0];
    const float* h0   = (const float*)d_in[1];
    const float* c0   = (const float*)d_in[2];
    const float* Wih  = (const float*)d_in[3];
    const float* Whh  = (const float*)d_in[4];
    const float* bih  = (const float*)d_in[5];
    const float* bhh  = (const float*)d_in[6];
    const float* Wout = (const float*)d_in[7];
    const float* bout = (const float*)d_in[8];

    float* d = (float*)d_out;
    const long long BT = (long long)B_ * T_;

    float* out0 = d;
    float* hs = d;
    int write_out0 = 1, write_hs = 1;
    if ((long long)out_size >= BT * (H_ + 1)) {
        // concat(output [B,T,1], hs [B,T,H]) — expected case
        out0 = d;
        hs = d + BT;
    } else if ((long long)out_size == BT * H_) {
        // only hidden states expected
        hs = d;
        write_out0 = 0;
    } else {
        // only head output expected
        out0 = d;
        write_hs = 0;
    }

    lstm_fused_kernel<<<B_, 256>>>(x, h0, c0, Wih, Whh, bih, bhh, Wout, bout,
                                   out0, hs, write_out0, write_hs);
}

// round 3
// speedup vs baseline: 1.1782x; 1.1782x over previous
#include <cuda_runtime.h>

// LSTM: B=512, T=512, D=32, H=64.  One CTA (256 threads) per batch element.
// Thread g owns gate row g with W_ih[g,:] + W_hh[g,:] register-resident as
// f32x2 pairs (96 regs).  Per step: 48 fma.rn.f32x2 dot from SMEM broadcasts,
// unified activation A*sigmoid(K*pre)+C, STS; threads 0..63 update c,h and
// store hs.  The sigmoid head over hs runs as a separate parallel kernel.

#define B_ 512
#define T_ 512
#define D_ 32
#define H_ 64

typedef unsigned long long u64;

__device__ __forceinline__ u64 fma2(u64 a, u64 b, u64 c) {
    u64 d;
    asm("fma.rn.f32x2 %0, %1, %2, %3;" : "=l"(d) : "l"(a), "l"(b), "l"(c));
    return d;
}
__device__ __forceinline__ u64 add2(u64 a, u64 b) {
    u64 d;
    asm("add.rn.f32x2 %0, %1, %2;" : "=l"(d) : "l"(a), "l"(b));
    return d;
}
__device__ __forceinline__ float lo32(u64 a) { return __uint_as_float((unsigned)a); }
__device__ __forceinline__ float hi32(u64 a) { return __uint_as_float((unsigned)(a >> 32)); }

__device__ __forceinline__ float sigmoid_(float x) {
    // 1/(1+e^-x); x << 0: e^-x -> inf, __fdividef(1,inf)=0 (correct limit)
    return __fdividef(1.f, 1.f + __expf(-x));
}
__device__ __forceinline__ float tanh_(float x) {
    // sign-safe: tanh(|x|) = 1 - 2/(e^{2|x|}+1); e -> inf gives exactly 1.
    float ax = fabsf(x);
    float t = 1.f - __fdividef(2.f, __expf(2.f * ax) + 1.f);
    return copysignf(t, x);
}

__global__ __launch_bounds__(256, 2) void lstm_fused_kernel(
    const float* __restrict__ x,     // [B,T,D]
    const float* __restrict__ h0,    // [1,B,H]
    const float* __restrict__ c0,    // [1,B,H]
    const float* __restrict__ Wih,   // [4H,D]
    const float* __restrict__ Whh,   // [4H,H]
    const float* __restrict__ bih,   // [4H]
    const float* __restrict__ bhh,   // [4H]
    float* __restrict__ hs)          // [B,T,H]
{
    __shared__ __align__(16) float h_sm[H_];
    __shared__ __align__(16) float x_sm[2][D_];
    __shared__ __align__(16) float act_sm[256];

    const int b = blockIdx.x;
    const int tid = threadIdx.x;

    // ---- weights -> registers as packed f32x2 ----
    u64 wih[16], whh[32];
    {
        const ulonglong2* p = reinterpret_cast<const ulonglong2*>(Wih + tid * D_);
#pragma unroll
        for (int q = 0; q < 8; q++) {
            ulonglong2 v = p[q];
            wih[2 * q] = v.x;
            wih[2 * q + 1] = v.y;
        }
        const ulonglong2* p2 = reinterpret_cast<const ulonglong2*>(Whh + tid * H_);
#pragma unroll
        for (int q = 0; q < 16; q++) {
            ulonglong2 v = p2[q];
            whh[2 * q] = v.x;
            whh[2 * q + 1] = v.y;
        }
    }
    // unified activation: gate block 2 (candidate) uses tanh = 2*sigmoid(2x)-1
    const bool is_tanh = ((tid >> 6) == 2);
    const float K = is_tanh ? 2.f : 1.f;
    const float A = is_tanh ? 2.f : 1.f;
    const float C = is_tanh ? -1.f : 0.f;
    const float bias = bih[tid] + bhh[tid];

    float c = 0.f;
    float* hs_ptr = hs + (long long)b * T_ * H_ + tid;   // valid use only if tid<64
    if (tid < H_) {
        c = c0[b * H_ + tid];
        h_sm[tid] = h0[b * H_ + tid];
    }
    const float* x_ptr = x + (long long)b * T_ * D_;
    if (tid >= 224) x_sm[0][tid - 224] = x_ptr[tid - 224];  // warp 7 stages x_0
    __syncthreads();

    for (int t = 0; t < T_; t++) {
        // prefetch x_{t+1} (LDG issued before the dot; STS in the tail phase)
        float xn = 0.f;
        if (tid >= 224) {
            const float* nx = x_ptr + (t + 1 < T_ ? (t + 1) : t) * D_;
            xn = nx[tid - 224];
        }

        // fused pre-activation: W_ih[g,:]@x_t + W_hh[g,:]@h + bias
        u64 a0 = 0, a1 = 0, a2 = 0, a3 = 0;
        const ulonglong2* xv = reinterpret_cast<const ulonglong2*>(x_sm[t & 1]);
#pragma unroll
        for (int q = 0; q < 8; q++) {
            ulonglong2 v = xv[q];  // LDS.128 broadcast
            a0 = fma2(wih[2 * q], v.x, a0);
            a1 = fma2(wih[2 * q + 1], v.y, a1);
        }
        const ulonglong2* hv = reinterpret_cast<const ulonglong2*>(h_sm);
#pragma unroll
        for (int q = 0; q < 16; q++) {
            ulonglong2 v = hv[q];  // LDS.128 broadcast
            a2 = fma2(whh[2 * q], v.x, a2);
            a3 = fma2(whh[2 * q + 1], v.y, a3);
        }
        u64 s = add2(add2(a0, a1), add2(a2, a3));
        float pre = lo32(s) + hi32(s) + bias;

        act_sm[tid] = fmaf(A, sigmoid_(K * pre), C);
        __syncthreads();  // gates visible; x_sm[t&1] free to overwrite

        if (tid >= 224) x_sm[(t + 1) & 1][tid - 224] = xn;
        if (tid < H_) {  // state update (warps 0-1)
            float iv = act_sm[tid];
            float fv = act_sm[H_ + tid];
            float gv = act_sm[2 * H_ + tid];
            float ov = act_sm[3 * H_ + tid];
            c = fv * c + iv * gv;
            float h = ov * tanh_(c);
            h_sm[tid] = h;
            hs_ptr[0] = h;
            hs_ptr += H_;
        }
        __syncthreads();  // h_sm + next-x visible
    }
}

// Epilogue: out0[b,t] = sigmoid( dot(hs[b,t,:], Wout) + bout ).
// One thread per (b,t) row; rows are 256B contiguous -> full-line DRAM reads.
__global__ __launch_bounds__(256) void head_kernel(
    const float* __restrict__ hs,    // [B*T, H]
    const float* __restrict__ Wout,  // [H]
    const float* __restrict__ bout,  // [1]
    float* __restrict__ out0)        // [B*T]
{
    __shared__ __align__(16) float w_sm[H_];
    if (threadIdx.x < H_) w_sm[threadIdx.x] = Wout[threadIdx.x];
    __syncthreads();

    long long row = (long long)blockIdx.x * blockDim.x + threadIdx.x;
    if (row >= (long long)B_ * T_) return;

    const float4* hv = reinterpret_cast<const float4*>(hs + row * H_);
    const float4* wv = reinterpret_cast<const float4*>(w_sm);
    float acc = 0.f;
#pragma unroll
    for (int q = 0; q < H_ / 4; q++) {
        float4 h4 = hv[q];
        float4 w4 = wv[q];
        acc += h4.x * w4.x + h4.y * w4.y + h4.z * w4.z + h4.w * w4.w;
    }
    out0[row] = sigmoid_(acc + bout[0]);
}

extern "C" void kernel_launch(void* const* d_in, const int* in_sizes, int n_in,
                              void* d_out, int out_size) {
    const float* x    = (const float*)d_in[0];
    const float* h0   = (const float*)d_in[1];
    const float* c0   = (const float*)d_in[2];
    const float* Wih  = (const float*)d_in[3];
    const float* Whh  = (const float*)d_in[4];
    const float* bih  = (const float*)d_in[5];
    const float* bhh  = (const float*)d_in[6];
    const float* Wout = (const float*)d_in[7];
    const float* bout = (const float*)d_in[8];

    float* d = (float*)d_out;
    const long long BT = (long long)B_ * T_;

    float* out0 = d;
    float* hs = d;
    int write_out0 = 1;
    if ((long long)out_size >= BT * (H_ + 1)) {
        out0 = d;           // concat(output [B,T,1], hs [B,T,H]) — verified case
        hs = d + BT;
    } else if ((long long)out_size == BT * H_) {
        hs = d;
        write_out0 = 0;
    }

    lstm_fused_kernel<<<B_, 256>>>(x, h0, c0, Wih, Whh, bih, bhh, hs);
    if (write_out0) {
        int grid = (int)((BT + 255) / 256);
        head_kernel<<<grid, 256>>>(hs, Wout, bout, out0);
    }
}